// round 16
// baseline (speedup 1.0000x reference)
#include <cuda_runtime.h>
#include <cuda_fp16.h>
#include <cstdint>

// ============================================================
// spikes = ((X @ ternarize(S)^T) >= 1)
// Round 16 = round-13 structure (698.5us proven: conv_all ->
// persistent gemm_hi -> flat high-occupancy fixup) with the lo
// limb stored as s8 (scale 2^19) instead of s16 (scale 2^27):
//  - |x - f16(x)| <= 2^-12 so lo*2^19 fits s8 (clamp +-127);
//    quantization sigma ~2.8e-5 << reference fp32 noise 6.5e-5.
//  - fixup reads 8KB/entry (dp4a) instead of 12KB (dp2a).
//  - conv writes 32MB lo instead of 64MB.
// Round-15 in-gemm work-stealing tail REVERTED (no overlap
// window in a balanced persistent grid; occ-starved dp2a).
// ============================================================

#define M_TOT 8192
#define N_TOT 4096
#define K_SRC 4096
#define BM 128
#define BN 256
#define NCHUNKS 64                  // K64 fp16 per chunk (128B rows)
#define STAGES 4
#define A_STAGE 16384               // 128 rows x 128B
#define B_STAGE 32768               // 256 rows x 128B
#define STAGE_BYTES (A_STAGE + B_STAGE)       // 48KB
#define SMEM_TOTAL (STAGES * STAGE_BYTES)     // 192KB
#define NSM 148
#define NTILES ((M_TOT / BM) * (N_TOT / BN))  // 1024
#define LIST_CAP (1u << 21)
#define MARG_LO 0.97f
#define MARG_HI 1.03f

// scratch
__device__ __align__(128) unsigned char g_Ahi[64ull * NCHUNKS * A_STAGE];  // 64MB swizzled hi
__device__ __align__(128) unsigned char g_B[16ull * NCHUNKS * B_STAGE];    // 32MB swizzled w f16
__device__ __align__(128) signed char g_lo8[(size_t)M_TOT * K_SRC];        // 32MB plain lo s8
__device__ __align__(128) signed char g_w8[(size_t)N_TOT * K_SRC];         // 16MB plain w s8
__device__ unsigned int g_cnt;
__device__ unsigned int g_mn[LIST_CAP];
__device__ float g_hs[LIST_CAP];

__device__ __forceinline__ uint32_t smem_u32(const void* p) {
    uint32_t a;
    asm("{ .reg .u64 t; cvta.to.shared.u64 t, %1; cvt.u32.u64 %0, t; }" : "=r"(a) : "l"(p));
    return a;
}
__device__ __forceinline__ uint32_t sw128(uint32_t off) {
    return off ^ ((off >> 3) & 0x70);
}

#define MBAR_INIT(addr, cnt) \
    asm volatile("mbarrier.init.shared.b64 [%0], %1;" :: "r"(addr), "r"(cnt) : "memory")
#define MBAR_ARRIVE(addr) \
    asm volatile("mbarrier.arrive.shared.b64 _, [%0];" :: "r"(addr) : "memory")
#define MBAR_EXPECT_TX(addr, bytes) \
    asm volatile("mbarrier.arrive.expect_tx.shared.b64 _, [%0], %1;" \
                 :: "r"(addr), "r"(bytes) : "memory")
#define MBAR_WAIT(addr, parity) do { \
    uint32_t _m = (addr); uint32_t _p = (parity); uint32_t _d; \
    asm volatile("{\n\t.reg .pred p;\n\t" \
        "mbarrier.try_wait.parity.acquire.cta.shared::cta.b64 p, [%1], %2;\n\t" \
        "selp.b32 %0, 1, 0, p;\n\t}" : "=r"(_d) : "r"(_m), "r"(_p) : "memory"); \
    if (!_d) { \
        asm volatile("{\n\t.reg .pred P1;\n\tWL_%=:\n\t" \
            "mbarrier.try_wait.parity.acquire.cta.shared::cta.b64 P1, [%0], %1, 0x989680;\n\t" \
            "@P1 bra.uni WD_%=;\n\tbra.uni WL_%=;\n\tWD_%=:\n\t}" \
            :: "r"(_m), "r"(_p) : "memory"); \
    } } while (0)
#define CP_BULK(dst, src, bytes, mbar) \
    asm volatile("cp.async.bulk.shared::cluster.global.mbarrier::complete_tx::bytes " \
                 "[%0], [%1], %2, [%3];" \
                 :: "r"(dst), "l"(src), "r"(bytes), "r"(mbar) : "memory")
#define FENCE_ASYNC_SHARED() asm volatile("fence.proxy.async.shared::cta;" ::: "memory")

#define LDSM4(r0, r1, r2, r3, addr) \
    asm volatile("ldmatrix.sync.aligned.m8n8.x4.shared.b16 {%0,%1,%2,%3}, [%4];" \
                 : "=r"(r0), "=r"(r1), "=r"(r2), "=r"(r3) : "r"(addr))
#define MMA16816(c, a, b0, b1) \
    asm volatile("mma.sync.aligned.m16n8k16.row.col.f32.f16.f16.f32 " \
                 "{%0,%1,%2,%3}, {%4,%5,%6,%7}, {%8,%9}, {%0,%1,%2,%3};" \
                 : "+f"((c)[0]), "+f"((c)[1]), "+f"((c)[2]), "+f"((c)[3]) \
                 : "r"((a)[0]), "r"((a)[1]), "r"((a)[2]), "r"((a)[3]), \
                   "r"(b0), "r"(b1))

// ---------------- merged convert kernel ----------------
__global__ __launch_bounds__(256)
void conv_all(const float* __restrict__ X, const float* __restrict__ S) {
    if (blockIdx.x == 0 && blockIdx.y == 0 && threadIdx.x == 0) g_cnt = 0;

    const int tid = threadIdx.x;
    const int c = blockIdx.y;            // chunk 0..63

    if (blockIdx.x < 64) {
        const int t = blockIdx.x;        // m128 tile
        const int r = tid >> 1, h = tid & 1;

        const float4* src = reinterpret_cast<const float4*>(
            X + (size_t)(t * 128 + r) * K_SRC + c * 64 + h * 32);
        unsigned char* dhi = g_Ahi + ((size_t)t * NCHUNKS + c) * A_STAGE;
        signed char* dlo = g_lo8 + (size_t)(t * 128 + r) * K_SRC + c * 64 + h * 32;

        uint32_t lo8[8];
#pragma unroll
        for (int j = 0; j < 4; j++) {
            float4 f0 = src[j * 2], f1 = src[j * 2 + 1];
            float xs[8] = {f0.x, f0.y, f0.z, f0.w, f1.x, f1.y, f1.z, f1.w};
            __half2 hh[4];
            uint32_t lb[8];
#pragma unroll
            for (int e = 0; e < 4; e++) {
                __half a = __float2half_rn(xs[2 * e]);
                __half b = __float2half_rn(xs[2 * e + 1]);
                hh[e] = __halves2half2(a, b);
                int la = __float2int_rn((xs[2 * e]     - __half2float(a)) * 524288.0f);
                int lbv = __float2int_rn((xs[2 * e + 1] - __half2float(b)) * 524288.0f);
                la = max(min(la, 127), -127);
                lbv = max(min(lbv, 127), -127);
                lb[2 * e]     = (uint32_t)la & 0xFFu;
                lb[2 * e + 1] = (uint32_t)lbv & 0xFFu;
            }
            lo8[j * 2]     = lb[0] | (lb[1] << 8) | (lb[2] << 16) | (lb[3] << 24);
            lo8[j * 2 + 1] = lb[4] | (lb[5] << 8) | (lb[6] << 16) | (lb[7] << 24);
            uint32_t sw = sw128((uint32_t)r * 128 + h * 64 + j * 16);
            *reinterpret_cast<uint4*>(dhi + sw) = *reinterpret_cast<uint4*>(hh);
        }
        *reinterpret_cast<uint4*>(dlo)     = make_uint4(lo8[0], lo8[1], lo8[2], lo8[3]);
        *reinterpret_cast<uint4*>(dlo + 16) = make_uint4(lo8[4], lo8[5], lo8[6], lo8[7]);
    } else if (blockIdx.x < 80) {
        const int nt = blockIdx.x - 64;  // n256 tile
        const int r = tid;               // row 0..255

        const float4* src = reinterpret_cast<const float4*>(
            S + (size_t)(nt * 256 + r) * K_SRC + c * 64);
        unsigned char* dst = g_B + ((size_t)nt * NCHUNKS + c) * B_STAGE;
        signed char* d8 = g_w8 + (size_t)(nt * 256 + r) * K_SRC + c * 64;

        uint32_t pk[16];
#pragma unroll
        for (int j = 0; j < 8; j++) {
            float4 f0 = src[j * 2], f1 = src[j * 2 + 1];
            float xs[8] = {f0.x, f0.y, f0.z, f0.w, f1.x, f1.y, f1.z, f1.w};
            __half2 ww[4];
            uint32_t b0 = 0, b1 = 0;
#pragma unroll
            for (int e = 0; e < 4; e++) {
                float wa = (xs[2 * e]     > 1.0f) ? 1.0f : ((xs[2 * e]     < -1.0f) ? -1.0f : 0.0f);
                float wb = (xs[2 * e + 1] > 1.0f) ? 1.0f : ((xs[2 * e + 1] < -1.0f) ? -1.0f : 0.0f);
                ww[e] = __halves2half2(__float2half_rn(wa), __float2half_rn(wb));
                uint32_t ba = (xs[2 * e]     > 1.0f) ? 1u : ((xs[2 * e]     < -1.0f) ? 0xFFu : 0u);
                uint32_t bb = (xs[2 * e + 1] > 1.0f) ? 1u : ((xs[2 * e + 1] < -1.0f) ? 0xFFu : 0u);
                if (e < 2) b0 |= (ba << (e * 16)) | (bb << (e * 16 + 8));
                else       b1 |= (ba << ((e - 2) * 16)) | (bb << ((e - 2) * 16 + 8));
            }
            uint32_t sw = sw128((uint32_t)r * 128 + j * 16);
            *reinterpret_cast<uint4*>(dst + sw) = *reinterpret_cast<uint4*>(ww);
            pk[j * 2] = b0; pk[j * 2 + 1] = b1;
        }
#pragma unroll
        for (int q = 0; q < 4; q++)
            *reinterpret_cast<uint4*>(d8 + q * 16) =
                make_uint4(pk[q * 4], pk[q * 4 + 1], pk[q * 4 + 2], pk[q * 4 + 3]);
    }
}

// ---------------- persistent hi GEMM (round-8 form) ----------------
__device__ __forceinline__ void fill_chunk(uint32_t usmem, uint32_t mbar, int bx, int L) {
    const int w = L >> 6, c = L & 63;
    const int t = bx + w * NSM;
    const int m = t >> 4, n = t & 15;
    const uint32_t dA = usmem + (L & 3) * STAGE_BYTES;
    MBAR_EXPECT_TX(mbar, (uint32_t)STAGE_BYTES);
    CP_BULK(dA,           g_Ahi + ((size_t)m * NCHUNKS + c) * A_STAGE, A_STAGE, mbar);
    CP_BULK(dA + A_STAGE, g_B  + ((size_t)n * NCHUNKS + c) * B_STAGE, B_STAGE, mbar);
}

__global__ __launch_bounds__(256, 1)
void gemm_hi(float* __restrict__ Out) {
    extern __shared__ __align__(128) unsigned char smem[];
    __shared__ __align__(8) uint64_t s_mbar[2 * STAGES];

    const int tid = threadIdx.x;
    const int lane = tid & 31;
    const int wid = tid >> 5;
    const int wm = wid & 1;
    const int wn = wid >> 1;
    const int bx = blockIdx.x;              // 0..147 persistent

    const int nT = (NTILES - bx + NSM - 1) / NSM;
    const int totL = nT * NCHUNKS;

    const uint32_t usmem = smem_u32(smem);
    uint32_t mb_full[STAGES], mb_empty[STAGES];
#pragma unroll
    for (int s = 0; s < STAGES; s++) {
        mb_full[s]  = smem_u32(&s_mbar[s]);
        mb_empty[s] = smem_u32(&s_mbar[s + STAGES]);
    }

    if (tid == 0) {
#pragma unroll
        for (int s = 0; s < STAGES; s++) {
            MBAR_INIT(mb_full[s], 1);
            MBAR_INIT(mb_empty[s], 8);
        }
        FENCE_ASYNC_SHARED();
    }
    __syncthreads();

    if (tid == 0) {
#pragma unroll
        for (int p = 0; p < STAGES; p++) fill_chunk(usmem, mb_full[p], bx, p);
    }

    uint32_t rowoffA[4], rowoffB[4];
#pragma unroll
    for (int mt = 0; mt < 4; mt++)
        rowoffA[mt] = (uint32_t)(wm * 64 + mt * 16 + (lane & 15)) * 128;
#pragma unroll
    for (int nt = 0; nt < 4; nt++)
        rowoffB[nt] = (uint32_t)(wn * 64 + nt * 16 + ((lane >> 4) * 8 + (lane & 7))) * 128;
    const uint32_t xorv = (uint32_t)(lane & 7) * 16;
    const uint32_t colA_half = (uint32_t)(lane >> 4);
    const uint32_t colB_half = (uint32_t)((lane >> 3) & 1);

    float acc[4][8][4];
#pragma unroll
    for (int mt = 0; mt < 4; mt++)
#pragma unroll
        for (int nt = 0; nt < 8; nt++)
#pragma unroll
            for (int e = 0; e < 4; e++) acc[mt][nt][e] = 0.0f;

    for (int L = 0; L < totL; L++) {
        const int st = L & 3;
        const int ph = (L >> 2) & 1;
        MBAR_WAIT(mb_full[st], ph);

        const uint32_t uA = usmem + st * STAGE_BYTES;
        const uint32_t uB = uA + A_STAGE;

#pragma unroll
        for (int ks = 0; ks < 4; ks++) {
            uint32_t a[4][4], b[4][4];
            const uint32_t cA = ((uint32_t)(ks * 2) + colA_half) * 16;
            const uint32_t cB = ((uint32_t)(ks * 2) + colB_half) * 16;
#pragma unroll
            for (int mt = 0; mt < 4; mt++)
                LDSM4(a[mt][0], a[mt][1], a[mt][2], a[mt][3],
                      uA + rowoffA[mt] + (cA ^ xorv));
#pragma unroll
            for (int nt = 0; nt < 4; nt++)
                LDSM4(b[nt][0], b[nt][1], b[nt][2], b[nt][3],
                      uB + rowoffB[nt] + (cB ^ xorv));
#pragma unroll
            for (int mt = 0; mt < 4; mt++)
#pragma unroll
                for (int nt = 0; nt < 4; nt++) {
                    MMA16816(acc[mt][2 * nt],     a[mt], b[nt][0], b[nt][1]);
                    MMA16816(acc[mt][2 * nt + 1], a[mt], b[nt][2], b[nt][3]);
                }
        }

        if (lane == 0) MBAR_ARRIVE(mb_empty[st]);

        if (tid == 0 && L + STAGES < totL) {
            MBAR_WAIT(mb_empty[st], ph);
            fill_chunk(usmem, mb_full[st], bx, L + STAGES);
        }

        if ((L & 63) == 63) {
            const int t = bx + (L >> 6) * NSM;
            const int m0 = (t >> 4) * BM;
            const int n0 = (t & 15) * BN;
#pragma unroll
            for (int mt = 0; mt < 4; mt++) {
                const int row = m0 + wm * 64 + mt * 16 + (lane >> 2);
#pragma unroll
                for (int nt = 0; nt < 8; nt++) {
                    const int col = n0 + wn * 64 + nt * 8 + (lane & 3) * 2;
                    const float s0 = acc[mt][nt][0], s1 = acc[mt][nt][1];
                    const float s2 = acc[mt][nt][2], s3 = acc[mt][nt][3];
                    *reinterpret_cast<float2*>(Out + (size_t)row * N_TOT + col) =
                        make_float2((s0 >= 1.0f) ? 1.0f : 0.0f, (s1 >= 1.0f) ? 1.0f : 0.0f);
                    *reinterpret_cast<float2*>(Out + (size_t)(row + 8) * N_TOT + col) =
                        make_float2((s2 >= 1.0f) ? 1.0f : 0.0f, (s3 >= 1.0f) ? 1.0f : 0.0f);
                    if (s0 > MARG_LO && s0 < MARG_HI) {
                        unsigned int i = atomicAdd(&g_cnt, 1u);
                        if (i < LIST_CAP) { g_mn[i] = ((unsigned)row << 12) | (unsigned)col; g_hs[i] = s0; }
                    }
                    if (s1 > MARG_LO && s1 < MARG_HI) {
                        unsigned int i = atomicAdd(&g_cnt, 1u);
                        if (i < LIST_CAP) { g_mn[i] = ((unsigned)row << 12) | (unsigned)(col + 1); g_hs[i] = s1; }
                    }
                    if (s2 > MARG_LO && s2 < MARG_HI) {
                        unsigned int i = atomicAdd(&g_cnt, 1u);
                        if (i < LIST_CAP) { g_mn[i] = ((unsigned)(row + 8) << 12) | (unsigned)col; g_hs[i] = s2; }
                    }
                    if (s3 > MARG_LO && s3 < MARG_HI) {
                        unsigned int i = atomicAdd(&g_cnt, 1u);
                        if (i < LIST_CAP) { g_mn[i] = ((unsigned)(row + 8) << 12) | (unsigned)(col + 1); g_hs[i] = s3; }
                    }
#pragma unroll
                    for (int e = 0; e < 4; e++) acc[mt][nt][e] = 0.0f;
                }
            }
        }
    }
}

// ---------------- flat fixup (dp4a, s8 lo) ----------------
__global__ __launch_bounds__(256)
void fixup(float* __restrict__ Out) {
    const int lane = threadIdx.x & 31;
    const int gw = blockIdx.x * (blockDim.x >> 5) + (threadIdx.x >> 5);
    const int nwarps = gridDim.x * (blockDim.x >> 5);
    const unsigned int cnt = min(g_cnt, LIST_CAP);

    for (unsigned int i = gw; i < cnt; i += nwarps) {
        const unsigned int mn = g_mn[i];
        const float hs = g_hs[i];
        const int m = mn >> 12, n = mn & 4095;

        const uint4* lp = reinterpret_cast<const uint4*>(g_lo8 + (size_t)m * K_SRC) + lane * 8;
        const uint4* wp = reinterpret_cast<const uint4*>(g_w8 + (size_t)n * K_SRC) + lane * 8;

        int s = 0;
#pragma unroll
        for (int q = 0; q < 8; q++) {
            uint4 lv = lp[q];
            uint4 wv = wp[q];
            s = __dp4a((int)lv.x, (int)wv.x, s);
            s = __dp4a((int)lv.y, (int)wv.y, s);
            s = __dp4a((int)lv.z, (int)wv.z, s);
            s = __dp4a((int)lv.w, (int)wv.w, s);
        }
#pragma unroll
        for (int off = 16; off; off >>= 1)
            s += __shfl_xor_sync(0xFFFFFFFFu, s, off);

        if (lane == 0) {
            const float tot = hs + (float)s * 1.9073486328125e-6f;   // 2^-19
            Out[(size_t)m * N_TOT + n] = (tot >= 1.0f) ? 1.0f : 0.0f;
        }
    }
}

// ---------------- host ----------------
extern "C" void kernel_launch(void* const* d_in, const int* in_sizes, int n_in,
                              void* d_out, int out_size) {
    const float* X = (const float*)d_in[0];   // [8192, 4096]
    const float* S = (const float*)d_in[1];   // [4096, 4096]
    float* Out = (float*)d_out;

    cudaFuncSetAttribute(gemm_hi, cudaFuncAttributeMaxDynamicSharedMemorySize, SMEM_TOTAL);

    conv_all<<<dim3(80, 64), 256>>>(X, S);
    gemm_hi<<<NSM, 256, SMEM_TOTAL>>>(Out);
    fixup<<<2048, 256>>>(Out);
}

// round 17
// speedup vs baseline: 1.4785x; 1.4785x over previous
#include <cuda_runtime.h>
#include <cuda_fp16.h>
#include <cstdint>

// ============================================================
// spikes = ((X @ ternarize(S)^T) >= 1)
// FINAL (= round 13, measured 698.5us, rel_err 3.4757e-4):
//   conv_all: X -> fp16 hi (swizzled) + s16 lo (scale 2^27),
//             S -> ternary fp16 (swizzled) + s8.
//   gemm_hi:  persistent 148-CTA fp16 mma.sync GEMM (BN=256,
//             4-stage cp.async.bulk ring, inline tid==0
//             producer) at ~93% of the HMMA issue floor;
//             outputs with |hi_sum-1| < 0.03 appended to list.
//   fixup:    flat high-occupancy exact dp2a re-verification.
// Rounds 14 (epilogue-fused fixup: regs 255), 15 (work-stealing
// tail: no overlap window), 16 (s8 lo: numerics + perf) all
// REVERTED after falsification.
// ============================================================

#define M_TOT 8192
#define N_TOT 4096
#define K_SRC 4096
#define BM 128
#define BN 256
#define NCHUNKS 64                  // K64 fp16 per chunk (128B rows)
#define STAGES 4
#define A_STAGE 16384               // 128 rows x 128B
#define B_STAGE 32768               // 256 rows x 128B
#define STAGE_BYTES (A_STAGE + B_STAGE)       // 48KB
#define SMEM_TOTAL (STAGES * STAGE_BYTES)     // 192KB
#define NSM 148
#define NTILES ((M_TOT / BM) * (N_TOT / BN))  // 1024
#define LIST_CAP (1u << 21)
#define MARG_LO 0.97f
#define MARG_HI 1.03f

// scratch
__device__ __align__(128) unsigned char g_Ahi[64ull * NCHUNKS * A_STAGE];  // 64MB swizzled hi
__device__ __align__(128) unsigned char g_B[16ull * NCHUNKS * B_STAGE];    // 32MB swizzled w f16
__device__ __align__(128) short g_lo16[(size_t)M_TOT * K_SRC];             // 64MB plain lo s16
__device__ __align__(128) signed char g_w8[(size_t)N_TOT * K_SRC];         // 16MB plain w s8
__device__ unsigned int g_cnt;
__device__ unsigned int g_mn[LIST_CAP];
__device__ float g_hs[LIST_CAP];

__device__ __forceinline__ uint32_t smem_u32(const void* p) {
    uint32_t a;
    asm("{ .reg .u64 t; cvta.to.shared.u64 t, %1; cvt.u32.u64 %0, t; }" : "=r"(a) : "l"(p));
    return a;
}
__device__ __forceinline__ uint32_t sw128(uint32_t off) {
    return off ^ ((off >> 3) & 0x70);
}

#define MBAR_INIT(addr, cnt) \
    asm volatile("mbarrier.init.shared.b64 [%0], %1;" :: "r"(addr), "r"(cnt) : "memory")
#define MBAR_ARRIVE(addr) \
    asm volatile("mbarrier.arrive.shared.b64 _, [%0];" :: "r"(addr) : "memory")
#define MBAR_EXPECT_TX(addr, bytes) \
    asm volatile("mbarrier.arrive.expect_tx.shared.b64 _, [%0], %1;" \
                 :: "r"(addr), "r"(bytes) : "memory")
#define MBAR_WAIT(addr, parity) do { \
    uint32_t _m = (addr); uint32_t _p = (parity); uint32_t _d; \
    asm volatile("{\n\t.reg .pred p;\n\t" \
        "mbarrier.try_wait.parity.acquire.cta.shared::cta.b64 p, [%1], %2;\n\t" \
        "selp.b32 %0, 1, 0, p;\n\t}" : "=r"(_d) : "r"(_m), "r"(_p) : "memory"); \
    if (!_d) { \
        asm volatile("{\n\t.reg .pred P1;\n\tWL_%=:\n\t" \
            "mbarrier.try_wait.parity.acquire.cta.shared::cta.b64 P1, [%0], %1, 0x989680;\n\t" \
            "@P1 bra.uni WD_%=;\n\tbra.uni WL_%=;\n\tWD_%=:\n\t}" \
            :: "r"(_m), "r"(_p) : "memory"); \
    } } while (0)
#define CP_BULK(dst, src, bytes, mbar) \
    asm volatile("cp.async.bulk.shared::cluster.global.mbarrier::complete_tx::bytes " \
                 "[%0], [%1], %2, [%3];" \
                 :: "r"(dst), "l"(src), "r"(bytes), "r"(mbar) : "memory")
#define FENCE_ASYNC_SHARED() asm volatile("fence.proxy.async.shared::cta;" ::: "memory")

#define LDSM4(r0, r1, r2, r3, addr) \
    asm volatile("ldmatrix.sync.aligned.m8n8.x4.shared.b16 {%0,%1,%2,%3}, [%4];" \
                 : "=r"(r0), "=r"(r1), "=r"(r2), "=r"(r3) : "r"(addr))
#define MMA16816(c, a, b0, b1) \
    asm volatile("mma.sync.aligned.m16n8k16.row.col.f32.f16.f16.f32 " \
                 "{%0,%1,%2,%3}, {%4,%5,%6,%7}, {%8,%9}, {%0,%1,%2,%3};" \
                 : "+f"((c)[0]), "+f"((c)[1]), "+f"((c)[2]), "+f"((c)[3]) \
                 : "r"((a)[0]), "r"((a)[1]), "r"((a)[2]), "r"((a)[3]), \
                   "r"(b0), "r"(b1))

// ---------------- merged convert kernel ----------------
__global__ __launch_bounds__(256)
void conv_all(const float* __restrict__ X, const float* __restrict__ S) {
    if (blockIdx.x == 0 && blockIdx.y == 0 && threadIdx.x == 0) g_cnt = 0;

    const int tid = threadIdx.x;
    const int c = blockIdx.y;            // chunk 0..63

    if (blockIdx.x < 64) {
        const int t = blockIdx.x;        // m128 tile
        const int r = tid >> 1, h = tid & 1;

        const float4* src = reinterpret_cast<const float4*>(
            X + (size_t)(t * 128 + r) * K_SRC + c * 64 + h * 32);
        unsigned char* dhi = g_Ahi + ((size_t)t * NCHUNKS + c) * A_STAGE;
        short* dlo = g_lo16 + (size_t)(t * 128 + r) * K_SRC + c * 64 + h * 32;

        // front-batched loads: 8 x float4 = 32 floats
        float4 f[8];
#pragma unroll
        for (int j = 0; j < 8; j++) f[j] = src[j];

        __half2 hh[16];
        uint32_t lw[16];
#pragma unroll
        for (int e = 0; e < 16; e++) {
            const float x0 = (&f[e >> 1].x)[(e & 1) * 2];
            const float x1 = (&f[e >> 1].x)[(e & 1) * 2 + 1];
            __half a = __float2half_rn(x0);
            __half b = __float2half_rn(x1);
            hh[e] = __halves2half2(a, b);
            int la = __float2int_rn((x0 - __half2float(a)) * 134217728.0f);
            int lb = __float2int_rn((x1 - __half2float(b)) * 134217728.0f);
            la = max(min(la, 32767), -32768);
            lb = max(min(lb, 32767), -32768);
            lw[e] = ((uint32_t)la & 0xFFFFu) | ((uint32_t)lb << 16);
        }
#pragma unroll
        for (int j = 0; j < 4; j++) {
            uint32_t sw = sw128((uint32_t)r * 128 + h * 64 + j * 16);
            *reinterpret_cast<uint4*>(dhi + sw) = *reinterpret_cast<uint4*>(&hh[j * 4]);
            *reinterpret_cast<uint4*>(dlo + j * 8) =
                make_uint4(lw[j * 4], lw[j * 4 + 1], lw[j * 4 + 2], lw[j * 4 + 3]);
        }
    } else if (blockIdx.x < 80) {
        const int nt = blockIdx.x - 64;  // n256 tile
        const int r = tid;               // row 0..255

        const float4* src = reinterpret_cast<const float4*>(
            S + (size_t)(nt * 256 + r) * K_SRC + c * 64);
        unsigned char* dst = g_B + ((size_t)nt * NCHUNKS + c) * B_STAGE;
        signed char* d8 = g_w8 + (size_t)(nt * 256 + r) * K_SRC + c * 64;

        uint32_t pk[16];
#pragma unroll
        for (int half = 0; half < 2; half++) {
            // front-batched loads: 8 x float4 per half
            float4 f[8];
#pragma unroll
            for (int j = 0; j < 8; j++) f[j] = src[half * 8 + j];

#pragma unroll
            for (int j = 0; j < 4; j++) {
                __half2 ww[4];
                uint32_t b0 = 0, b1 = 0;
#pragma unroll
                for (int e = 0; e < 4; e++) {
                    const float x0 = (&f[j * 2 + (e >> 1)].x)[(e & 1) * 2];
                    const float x1 = (&f[j * 2 + (e >> 1)].x)[(e & 1) * 2 + 1];
                    float wa = (x0 > 1.0f) ? 1.0f : ((x0 < -1.0f) ? -1.0f : 0.0f);
                    float wb = (x1 > 1.0f) ? 1.0f : ((x1 < -1.0f) ? -1.0f : 0.0f);
                    ww[e] = __halves2half2(__float2half_rn(wa), __float2half_rn(wb));
                    uint32_t ba = (x0 > 1.0f) ? 1u : ((x0 < -1.0f) ? 0xFFu : 0u);
                    uint32_t bb = (x1 > 1.0f) ? 1u : ((x1 < -1.0f) ? 0xFFu : 0u);
                    if (e < 2) b0 |= (ba << (e * 16)) | (bb << (e * 16 + 8));
                    else       b1 |= (ba << ((e - 2) * 16)) | (bb << ((e - 2) * 16 + 8));
                }
                const int jj = half * 4 + j;
                uint32_t sw = sw128((uint32_t)r * 128 + jj * 16);
                *reinterpret_cast<uint4*>(dst + sw) = *reinterpret_cast<uint4*>(ww);
                pk[jj * 2] = b0; pk[jj * 2 + 1] = b1;
            }
        }
#pragma unroll
        for (int q = 0; q < 4; q++)
            *reinterpret_cast<uint4*>(d8 + q * 16) =
                make_uint4(pk[q * 4], pk[q * 4 + 1], pk[q * 4 + 2], pk[q * 4 + 3]);
    }
}

// ---------------- persistent hi GEMM (round-8 form) ----------------
__device__ __forceinline__ void fill_chunk(uint32_t usmem, uint32_t mbar, int bx, int L) {
    const int w = L >> 6, c = L & 63;
    const int t = bx + w * NSM;
    const int m = t >> 4, n = t & 15;
    const uint32_t dA = usmem + (L & 3) * STAGE_BYTES;
    MBAR_EXPECT_TX(mbar, (uint32_t)STAGE_BYTES);
    CP_BULK(dA,           g_Ahi + ((size_t)m * NCHUNKS + c) * A_STAGE, A_STAGE, mbar);
    CP_BULK(dA + A_STAGE, g_B  + ((size_t)n * NCHUNKS + c) * B_STAGE, B_STAGE, mbar);
}

__global__ __launch_bounds__(256, 1)
void gemm_hi(float* __restrict__ Out) {
    extern __shared__ __align__(128) unsigned char smem[];
    __shared__ __align__(8) uint64_t s_mbar[2 * STAGES];

    const int tid = threadIdx.x;
    const int lane = tid & 31;
    const int wid = tid >> 5;
    const int wm = wid & 1;
    const int wn = wid >> 1;
    const int bx = blockIdx.x;              // 0..147 persistent

    const int nT = (NTILES - bx + NSM - 1) / NSM;
    const int totL = nT * NCHUNKS;

    const uint32_t usmem = smem_u32(smem);
    uint32_t mb_full[STAGES], mb_empty[STAGES];
#pragma unroll
    for (int s = 0; s < STAGES; s++) {
        mb_full[s]  = smem_u32(&s_mbar[s]);
        mb_empty[s] = smem_u32(&s_mbar[s + STAGES]);
    }

    if (tid == 0) {
#pragma unroll
        for (int s = 0; s < STAGES; s++) {
            MBAR_INIT(mb_full[s], 1);
            MBAR_INIT(mb_empty[s], 8);
        }
        FENCE_ASYNC_SHARED();
    }
    __syncthreads();

    if (tid == 0) {
#pragma unroll
        for (int p = 0; p < STAGES; p++) fill_chunk(usmem, mb_full[p], bx, p);
    }

    uint32_t rowoffA[4], rowoffB[4];
#pragma unroll
    for (int mt = 0; mt < 4; mt++)
        rowoffA[mt] = (uint32_t)(wm * 64 + mt * 16 + (lane & 15)) * 128;
#pragma unroll
    for (int nt = 0; nt < 4; nt++)
        rowoffB[nt] = (uint32_t)(wn * 64 + nt * 16 + ((lane >> 4) * 8 + (lane & 7))) * 128;
    const uint32_t xorv = (uint32_t)(lane & 7) * 16;
    const uint32_t colA_half = (uint32_t)(lane >> 4);
    const uint32_t colB_half = (uint32_t)((lane >> 3) & 1);

    float acc[4][8][4];
#pragma unroll
    for (int mt = 0; mt < 4; mt++)
#pragma unroll
        for (int nt = 0; nt < 8; nt++)
#pragma unroll
            for (int e = 0; e < 4; e++) acc[mt][nt][e] = 0.0f;

    for (int L = 0; L < totL; L++) {
        const int st = L & 3;
        const int ph = (L >> 2) & 1;
        MBAR_WAIT(mb_full[st], ph);

        const uint32_t uA = usmem + st * STAGE_BYTES;
        const uint32_t uB = uA + A_STAGE;

#pragma unroll
        for (int ks = 0; ks < 4; ks++) {
            uint32_t a[4][4], b[4][4];
            const uint32_t cA = ((uint32_t)(ks * 2) + colA_half) * 16;
            const uint32_t cB = ((uint32_t)(ks * 2) + colB_half) * 16;
#pragma unroll
            for (int mt = 0; mt < 4; mt++)
                LDSM4(a[mt][0], a[mt][1], a[mt][2], a[mt][3],
                      uA + rowoffA[mt] + (cA ^ xorv));
#pragma unroll
            for (int nt = 0; nt < 4; nt++)
                LDSM4(b[nt][0], b[nt][1], b[nt][2], b[nt][3],
                      uB + rowoffB[nt] + (cB ^ xorv));
#pragma unroll
            for (int mt = 0; mt < 4; mt++)
#pragma unroll
                for (int nt = 0; nt < 4; nt++) {
                    MMA16816(acc[mt][2 * nt],     a[mt], b[nt][0], b[nt][1]);
                    MMA16816(acc[mt][2 * nt + 1], a[mt], b[nt][2], b[nt][3]);
                }
        }

        if (lane == 0) MBAR_ARRIVE(mb_empty[st]);

        if (tid == 0 && L + STAGES < totL) {
            MBAR_WAIT(mb_empty[st], ph);
            fill_chunk(usmem, mb_full[st], bx, L + STAGES);
        }

        if ((L & 63) == 63) {
            const int t = bx + (L >> 6) * NSM;
            const int m0 = (t >> 4) * BM;
            const int n0 = (t & 15) * BN;
#pragma unroll
            for (int mt = 0; mt < 4; mt++) {
                const int row = m0 + wm * 64 + mt * 16 + (lane >> 2);
#pragma unroll
                for (int nt = 0; nt < 8; nt++) {
                    const int col = n0 + wn * 64 + nt * 8 + (lane & 3) * 2;
                    const float s0 = acc[mt][nt][0], s1 = acc[mt][nt][1];
                    const float s2 = acc[mt][nt][2], s3 = acc[mt][nt][3];
                    *reinterpret_cast<float2*>(Out + (size_t)row * N_TOT + col) =
                        make_float2((s0 >= 1.0f) ? 1.0f : 0.0f, (s1 >= 1.0f) ? 1.0f : 0.0f);
                    *reinterpret_cast<float2*>(Out + (size_t)(row + 8) * N_TOT + col) =
                        make_float2((s2 >= 1.0f) ? 1.0f : 0.0f, (s3 >= 1.0f) ? 1.0f : 0.0f);
                    if (s0 > MARG_LO && s0 < MARG_HI) {
                        unsigned int i = atomicAdd(&g_cnt, 1u);
                        if (i < LIST_CAP) { g_mn[i] = ((unsigned)row << 12) | (unsigned)col; g_hs[i] = s0; }
                    }
                    if (s1 > MARG_LO && s1 < MARG_HI) {
                        unsigned int i = atomicAdd(&g_cnt, 1u);
                        if (i < LIST_CAP) { g_mn[i] = ((unsigned)row << 12) | (unsigned)(col + 1); g_hs[i] = s1; }
                    }
                    if (s2 > MARG_LO && s2 < MARG_HI) {
                        unsigned int i = atomicAdd(&g_cnt, 1u);
                        if (i < LIST_CAP) { g_mn[i] = ((unsigned)(row + 8) << 12) | (unsigned)col; g_hs[i] = s2; }
                    }
                    if (s3 > MARG_LO && s3 < MARG_HI) {
                        unsigned int i = atomicAdd(&g_cnt, 1u);
                        if (i < LIST_CAP) { g_mn[i] = ((unsigned)(row + 8) << 12) | (unsigned)(col + 1); g_hs[i] = s3; }
                    }
#pragma unroll
                    for (int e = 0; e < 4; e++) acc[mt][nt][e] = 0.0f;
                }
            }
        }
    }
}

// ---------------- flat fixup ----------------
__global__ __launch_bounds__(256)
void fixup(float* __restrict__ Out) {
    const int lane = threadIdx.x & 31;
    const int gw = blockIdx.x * (blockDim.x >> 5) + (threadIdx.x >> 5);
    const int nwarps = gridDim.x * (blockDim.x >> 5);
    const unsigned int cnt = min(g_cnt, LIST_CAP);

    for (unsigned int i = gw; i < cnt; i += nwarps) {
        const unsigned int mn = g_mn[i];
        const float hs = g_hs[i];
        const int m = mn >> 12, n = mn & 4095;

        const uint4* lp = reinterpret_cast<const uint4*>(g_lo16 + (size_t)m * K_SRC) + lane * 16;
        const uint4* wp = reinterpret_cast<const uint4*>(g_w8  + (size_t)n * K_SRC) + lane * 8;

        int s = 0;
#pragma unroll
        for (int q = 0; q < 8; q++) {
            uint4 wv = wp[q];
            uint4 l0 = lp[2 * q], l1 = lp[2 * q + 1];
            s = __dp2a_lo((int)l0.x, (int)wv.x, s);
            s = __dp2a_hi((int)l0.y, (int)wv.x, s);
            s = __dp2a_lo((int)l0.z, (int)wv.y, s);
            s = __dp2a_hi((int)l0.w, (int)wv.y, s);
            s = __dp2a_lo((int)l1.x, (int)wv.z, s);
            s = __dp2a_hi((int)l1.y, (int)wv.z, s);
            s = __dp2a_lo((int)l1.z, (int)wv.w, s);
            s = __dp2a_hi((int)l1.w, (int)wv.w, s);
        }
#pragma unroll
        for (int off = 16; off; off >>= 1)
            s += __shfl_xor_sync(0xFFFFFFFFu, s, off);

        if (lane == 0) {
            const float tot = hs + (float)s * 7.4505805969238281e-9f;   // 2^-27
            Out[(size_t)m * N_TOT + n] = (tot >= 1.0f) ? 1.0f : 0.0f;
        }
    }
}

// ---------------- host ----------------
extern "C" void kernel_launch(void* const* d_in, const int* in_sizes, int n_in,
                              void* d_out, int out_size) {
    const float* X = (const float*)d_in[0];   // [8192, 4096]
    const float* S = (const float*)d_in[1];   // [4096, 4096]
    float* Out = (float*)d_out;

    cudaFuncSetAttribute(gemm_hi, cudaFuncAttributeMaxDynamicSharedMemorySize, SMEM_TOTAL);

    conv_all<<<dim3(80, 64), 256>>>(X, S);
    gemm_hi<<<NSM, 256, SMEM_TOTAL>>>(Out);
    fixup<<<2048, 256>>>(Out);
}